// round 2
// baseline (speedup 1.0000x reference)
#include <cuda_runtime.h>
#include <cuda_bf16.h>

#define GSZ 64
#define TSH 3                 // log2(tile size in grid cells) -> tile = 8
#define TPD 8                 // tiles per dim
#define NT  (TPD * TPD * TPD) // 512 tiles
#define SLAB 11               // (8 + 3) taps span per dim
#define SLABN (SLAB * SLAB * SLAB) // 1331 float4 = 21296 B
#define CAP (1 << 20)

// Scratch (device globals: no allocation allowed in kernel_launch)
__device__ int    g_counts[NT];
__device__ int    g_offsets[NT + 1];
__device__ int    g_cursor[NT];
__device__ float4 g_pts[CAP];   // (zc, yc, xc, bitcast(point index))

// ---------------------------------------------------------------------------
// Shared index math: clamped base indices + tile id
// ---------------------------------------------------------------------------
__device__ __forceinline__ void base_idx(float zc, float yc, float xc,
                                         int& iz, int& iy, int& ix) {
    iz = min(max((int)floorf(zc), 1), GSZ - 3);
    iy = min(max((int)floorf(yc), 1), GSZ - 3);
    ix = min(max((int)floorf(xc), 1), GSZ - 3);
}

__device__ __forceinline__ int tile_id(int iz, int iy, int ix) {
    return ((((iz - 1) >> TSH) * TPD) + ((iy - 1) >> TSH)) * TPD + ((ix - 1) >> TSH);
}

// ---------------------------------------------------------------------------
// Pass 0: zero bin counters
// ---------------------------------------------------------------------------
__global__ void k_zero() {
    int i = threadIdx.x;
    if (i < NT) g_counts[i] = 0;
}

// ---------------------------------------------------------------------------
// Pass 1: histogram points into tiles
// ---------------------------------------------------------------------------
__global__ void __launch_bounds__(256) k_hist(const float* __restrict__ coords, int n) {
    int p = blockIdx.x * 256 + threadIdx.x;
    if (p >= n) return;
    float zc = coords[3 * p + 0];
    float yc = coords[3 * p + 1];
    float xc = coords[3 * p + 2];
    int iz, iy, ix;
    base_idx(zc, yc, xc, iz, iy, ix);
    atomicAdd(&g_counts[tile_id(iz, iy, ix)], 1);
}

// ---------------------------------------------------------------------------
// Pass 2: exclusive scan over 512 bins (single block)
// ---------------------------------------------------------------------------
__global__ void k_scan() {
    __shared__ int s[NT];
    int i = threadIdx.x;
    s[i] = g_counts[i];
    __syncthreads();
#pragma unroll
    for (int off = 1; off < NT; off <<= 1) {
        int v = (i >= off) ? s[i - off] : 0;
        __syncthreads();
        s[i] += v;
        __syncthreads();
    }
    g_offsets[i + 1] = s[i];
    if (i == 0) g_offsets[0] = 0;
    g_cursor[i] = (i == 0) ? 0 : s[i - 1];
}

// ---------------------------------------------------------------------------
// Pass 3: scatter point records into tile-sorted order
// ---------------------------------------------------------------------------
__global__ void __launch_bounds__(256) k_scatter(const float* __restrict__ coords, int n) {
    int p = blockIdx.x * 256 + threadIdx.x;
    if (p >= n) return;
    float zc = coords[3 * p + 0];
    float yc = coords[3 * p + 1];
    float xc = coords[3 * p + 2];
    int iz, iy, ix;
    base_idx(zc, yc, xc, iz, iy, ix);
    int t = tile_id(iz, iy, ix);
    int pos = atomicAdd(&g_cursor[t], 1);
    if (pos < CAP)
        g_pts[pos] = make_float4(zc, yc, xc, __int_as_float(p));
}

// ---------------------------------------------------------------------------
// Pass 4: one block per tile. Stage 11^3 knot slab in SMEM, evaluate all
// points of the tile. 4 lanes (quad) per point: lane lx loads the x-tap lx
// float4 of each of the 16 (z,y) rows -> one LDS.128 per row, conflict-light
// (row stride 176B cycles row-start banks through 8 distinct values).
// ---------------------------------------------------------------------------
__global__ void __launch_bounds__(256) k_process(const float* __restrict__ knots,
                                                 float* __restrict__ out) {
    __shared__ float4 slab[SLABN];

    int t  = blockIdx.x;
    int z0 = ((t >> 6) & 7) << TSH;
    int y0 = ((t >> 3) & 7) << TSH;
    int x0 = (t & 7) << TSH;

    const float4* k4 = reinterpret_cast<const float4*>(knots);
    for (int i = threadIdx.x; i < SLABN; i += 256) {
        int dz = i / (SLAB * SLAB);
        int r  = i - dz * (SLAB * SLAB);
        int dy = r / SLAB;
        int dx = r - dy * SLAB;
        int gz = min(z0 + dz, GSZ - 1);
        int gy = min(y0 + dy, GSZ - 1);
        int gx = min(x0 + dx, GSZ - 1);
        slab[i] = k4[(gz * GSZ + gy) * GSZ + gx];
    }
    __syncthreads();

    int beg = g_offsets[t];
    int end = g_offsets[t + 1];

    int q  = threadIdx.x >> 2;  // quad index within block (0..63)
    int lx = threadIdx.x & 3;   // x-tap lane within quad
    unsigned qmask = 0xFu << ((threadIdx.x & 31) & ~3);  // this quad's lanes

    for (int i = beg + q; i < end; i += 64) {
        float4 rec = g_pts[i];
        float zc = rec.x, yc = rec.y, xc = rec.z;
        int p = __float_as_int(rec.w);

        float fz = floorf(zc), fy = floorf(yc), fx = floorf(xc);
        int iz = (int)fz, iy = (int)fy, ix = (int)fx;
        float sz = zc - fz, sy = yc - fy, sx = xc - fx;
        iz = min(max(iz, 1), GSZ - 3);
        iy = min(max(iy, 1), GSZ - 3);
        ix = min(max(ix, 1), GSZ - 3);

        // Catmull-Rom basis
        float czv[4], cyv[4];
        czv[0] = sz * (-0.5f + sz * (1.0f - 0.5f * sz));
        czv[1] = 1.0f + sz * sz * (-2.5f + 1.5f * sz);
        czv[2] = sz * (0.5f + sz * (2.0f - 1.5f * sz));
        czv[3] = sz * sz * (0.5f * sz - 0.5f);
        cyv[0] = sy * (-0.5f + sy * (1.0f - 0.5f * sy));
        cyv[1] = 1.0f + sy * sy * (-2.5f + 1.5f * sy);
        cyv[2] = sy * (0.5f + sy * (2.0f - 1.5f * sy));
        cyv[3] = sy * sy * (0.5f * sy - 0.5f);
        float cx0 = sx * (-0.5f + sx * (1.0f - 0.5f * sx));
        float cx1 = 1.0f + sx * sx * (-2.5f + 1.5f * sx);
        float cx2 = sx * (0.5f + sx * (2.0f - 1.5f * sx));
        float cx3 = sx * sx * (0.5f * sx - 0.5f);

        int dz0 = iz - 1 - z0;
        int dy0 = iy - 1 - y0;
        int dx0 = ix - 1 - x0;
        const float4* sb = &slab[(dz0 * SLAB + dy0) * SLAB + dx0 + lx];

        float ax = 0.0f, ay = 0.0f, az = 0.0f, aw = 0.0f;
#pragma unroll
        for (int zi = 0; zi < 4; zi++) {
#pragma unroll
            for (int yi = 0; yi < 4; yi++) {
                float w = czv[zi] * cyv[yi];
                float4 k = sb[zi * (SLAB * SLAB) + yi * SLAB];
                ax = fmaf(w, k.x, ax);
                ay = fmaf(w, k.y, ay);
                az = fmaf(w, k.z, az);
                aw = fmaf(w, k.w, aw);
            }
        }

        float wx = (lx == 0) ? cx0 : (lx == 1) ? cx1 : (lx == 2) ? cx2 : cx3;
        ax *= wx; ay *= wx; az *= wx; aw *= wx;

#pragma unroll
        for (int d = 1; d < 4; d <<= 1) {
            ax += __shfl_xor_sync(qmask, ax, d);
            ay += __shfl_xor_sync(qmask, ay, d);
            az += __shfl_xor_sync(qmask, az, d);
            aw += __shfl_xor_sync(qmask, aw, d);
        }

        if (lx == 0)
            reinterpret_cast<float4*>(out)[p] = make_float4(ax, ay, az, aw);
    }
}

// ---------------------------------------------------------------------------
extern "C" void kernel_launch(void* const* d_in, const int* in_sizes, int n_in,
                              void* d_out, int out_size) {
    const float* coords = (const float*)d_in[0];  // [N,3] f32
    const float* knots  = (const float*)d_in[1];  // [64,64,64,4] f32
    float* out          = (float*)d_out;          // [N,4] f32

    int n = in_sizes[0] / 3;
    int pb = (n + 255) / 256;

    k_zero<<<1, NT>>>();
    k_hist<<<pb, 256>>>(coords, n);
    k_scan<<<1, NT>>>();
    k_scatter<<<pb, 256>>>(coords, n);
    k_process<<<NT, 256>>>(knots, out);
}

// round 3
// speedup vs baseline: 7.0000x; 7.0000x over previous
#include <cuda_runtime.h>
#include <cuda_fp16.h>

#define GSZ 64
#define NTILE (GSZ * GSZ * GSZ)   // 262144 tiles

// All-origins tile buffer: tile (z, y0, x0) = the 4x4 (y,x) patch of cells
// (z, y0..y0+3, x0..x0+3), 4 channels each, fp16 -> 16 cells * 8B = 128B
// = exactly one cache line. 32 MB total, L2-resident.
// Within a tile: cell c = dy*4+dx; uint4 j (j=0..7) holds cells 2j, 2j+1.
// Cell = {half2(ch0,ch1), half2(ch2,ch3)}.
__device__ uint4 g_tiles[NTILE * 8];

// ---------------------------------------------------------------------------
// Prep: build the tile buffer. One thread per (tile, dy): reads 4 cells
// (64B contiguous in knots), converts to fp16, writes 32B coalesced.
// ---------------------------------------------------------------------------
__global__ void __launch_bounds__(256) k_prep(const float* __restrict__ knots)
{
    int tid = blockIdx.x * 256 + threadIdx.x;     // NTILE*4 threads
    int t  = tid >> 2;
    int dy = tid & 3;
    if (t >= NTILE) return;

    int z  = t >> 12;
    int y0 = (t >> 6) & 63;
    int x0 = t & 63;
    int y  = min(y0 + dy, GSZ - 1);

    const float4* src = reinterpret_cast<const float4*>(knots) + (z * GSZ + y) * GSZ;

    uint4 o0, o1;
    {
        float4 k0 = src[min(x0 + 0, GSZ - 1)];
        float4 k1 = src[min(x0 + 1, GSZ - 1)];
        float4 k2 = src[min(x0 + 2, GSZ - 1)];
        float4 k3 = src[min(x0 + 3, GSZ - 1)];
        o0.x = __half2_raw(__floats2half2_rn(k0.x, k0.y)).x
             | ((unsigned)__half2_raw(__floats2half2_rn(k0.x, k0.y)).y << 16);
        // simpler: reinterpret
        __half2 h;
        h = __floats2half2_rn(k0.x, k0.y); o0.x = *reinterpret_cast<unsigned*>(&h);
        h = __floats2half2_rn(k0.z, k0.w); o0.y = *reinterpret_cast<unsigned*>(&h);
        h = __floats2half2_rn(k1.x, k1.y); o0.z = *reinterpret_cast<unsigned*>(&h);
        h = __floats2half2_rn(k1.z, k1.w); o0.w = *reinterpret_cast<unsigned*>(&h);
        h = __floats2half2_rn(k2.x, k2.y); o1.x = *reinterpret_cast<unsigned*>(&h);
        h = __floats2half2_rn(k2.z, k2.w); o1.y = *reinterpret_cast<unsigned*>(&h);
        h = __floats2half2_rn(k3.x, k3.y); o1.z = *reinterpret_cast<unsigned*>(&h);
        h = __floats2half2_rn(k3.z, k3.w); o1.w = *reinterpret_cast<unsigned*>(&h);
    }
    // cells (dy, dx=0,1) -> uint4 index dy*2 ; (dy, dx=2,3) -> dy*2+1
    g_tiles[t * 8 + dy * 2 + 0] = o0;
    g_tiles[t * 8 + dy * 2 + 1] = o1;
}

// ---------------------------------------------------------------------------
// Main: quad mapping. Lane lx handles y-tap dy=lx of its point: loads the
// two uint4 of that tile row (cells dx=0..3) for each of the 4 z-tiles.
// Per point: 4 tiles * 1 line each; 8 line-touches total across instructions.
// Quad-reduce 4 channels, lane 0 stores float4.
// ---------------------------------------------------------------------------
__global__ void __launch_bounds__(256) k_main(const float* __restrict__ coords,
                                              float* __restrict__ out,
                                              int n)
{
    int tid = blockIdx.x * 256 + threadIdx.x;
    int p  = tid >> 2;
    int lx = tid & 3;        // = dy tap of this lane
    if (p >= n) return;

    float zc = coords[p * 3 + 0];
    float yc = coords[p * 3 + 1];
    float xc = coords[p * 3 + 2];

    float fz = floorf(zc), fy = floorf(yc), fx = floorf(xc);
    int iz = (int)fz, iy = (int)fy, ix = (int)fx;
    float sz = zc - fz, sy = yc - fy, sx = xc - fx;
    iz = min(max(iz, 1), GSZ - 3);
    iy = min(max(iy, 1), GSZ - 3);
    ix = min(max(ix, 1), GSZ - 3);

    // Catmull-Rom basis
    float cz0 = sz * (-0.5f + sz * (1.0f - 0.5f * sz));
    float cz1 = 1.0f + sz * sz * (-2.5f + 1.5f * sz);
    float cz2 = sz * (0.5f + sz * (2.0f - 1.5f * sz));
    float cz3 = sz * sz * (0.5f * sz - 0.5f);
    float czv[4] = {cz0, cz1, cz2, cz3};

    // this lane only needs its own y coefficient (dy = lx)
    float cyl;
    {
        float c0 = sy * (-0.5f + sy * (1.0f - 0.5f * sy));
        float c1 = 1.0f + sy * sy * (-2.5f + 1.5f * sy);
        float c2 = sy * (0.5f + sy * (2.0f - 1.5f * sy));
        float c3 = sy * sy * (0.5f * sy - 0.5f);
        cyl = (lx == 0) ? c0 : (lx == 1) ? c1 : (lx == 2) ? c2 : c3;
    }

    float cx0 = sx * (-0.5f + sx * (1.0f - 0.5f * sx));
    float cx1 = 1.0f + sx * sx * (-2.5f + 1.5f * sx);
    float cx2 = sx * (0.5f + sx * (2.0f - 1.5f * sx));
    float cx3 = sx * sx * (0.5f * sx - 0.5f);

    int z0 = iz - 1, y0 = iy - 1, x0 = ix - 1;
    const uint4* tbase = g_tiles + (size_t)(((z0 * GSZ) + y0) * GSZ + x0) * 8 + lx * 2;

    float a0 = 0.f, a1 = 0.f, a2 = 0.f, a3 = 0.f;

#pragma unroll
    for (int zi = 0; zi < 4; zi++) {
        const uint4* tp = tbase + (size_t)zi * (GSZ * GSZ * 8);
        uint4 ra = tp[0];   // cells (lx, 0), (lx, 1)
        uint4 rb = tp[1];   // cells (lx, 2), (lx, 3)

        float w  = czv[zi] * cyl;
        float w0 = w * cx0, w1 = w * cx1, w2 = w * cx2, w3 = w * cx3;

        float2 f;
        f = __half22float2(*reinterpret_cast<__half2*>(&ra.x)); a0 = fmaf(w0, f.x, a0); a1 = fmaf(w0, f.y, a1);
        f = __half22float2(*reinterpret_cast<__half2*>(&ra.y)); a2 = fmaf(w0, f.x, a2); a3 = fmaf(w0, f.y, a3);
        f = __half22float2(*reinterpret_cast<__half2*>(&ra.z)); a0 = fmaf(w1, f.x, a0); a1 = fmaf(w1, f.y, a1);
        f = __half22float2(*reinterpret_cast<__half2*>(&ra.w)); a2 = fmaf(w1, f.x, a2); a3 = fmaf(w1, f.y, a3);
        f = __half22float2(*reinterpret_cast<__half2*>(&rb.x)); a0 = fmaf(w2, f.x, a0); a1 = fmaf(w2, f.y, a1);
        f = __half22float2(*reinterpret_cast<__half2*>(&rb.y)); a2 = fmaf(w2, f.x, a2); a3 = fmaf(w2, f.y, a3);
        f = __half22float2(*reinterpret_cast<__half2*>(&rb.z)); a0 = fmaf(w3, f.x, a0); a1 = fmaf(w3, f.y, a1);
        f = __half22float2(*reinterpret_cast<__half2*>(&rb.w)); a2 = fmaf(w3, f.x, a2); a3 = fmaf(w3, f.y, a3);
    }

    // reduce over the quad (y-taps)
#pragma unroll
    for (int d = 1; d < 4; d <<= 1) {
        a0 += __shfl_xor_sync(0xffffffffu, a0, d);
        a1 += __shfl_xor_sync(0xffffffffu, a1, d);
        a2 += __shfl_xor_sync(0xffffffffu, a2, d);
        a3 += __shfl_xor_sync(0xffffffffu, a3, d);
    }

    if (lx == 0)
        reinterpret_cast<float4*>(out)[p] = make_float4(a0, a1, a2, a3);
}

// ---------------------------------------------------------------------------
extern "C" void kernel_launch(void* const* d_in, const int* in_sizes, int n_in,
                              void* d_out, int out_size) {
    const float* coords = (const float*)d_in[0];  // [N,3] f32
    const float* knots  = (const float*)d_in[1];  // [64,64,64,4] f32
    float* out          = (float*)d_out;          // [N,4] f32

    int n = in_sizes[0] / 3;

    int prep_threads = NTILE * 4;
    k_prep<<<(prep_threads + 255) / 256, 256>>>(knots);

    long long total = 4LL * n;
    k_main<<<(int)((total + 255) / 256), 256>>>(coords, out, n);
}

// round 5
// speedup vs baseline: 8.5217x; 1.2174x over previous
#include <cuda_runtime.h>
#include <cuda_fp16.h>

#define GSZ 64
#define NTILE (GSZ * GSZ * GSZ)   // 262144 tiles

// All-origins tile buffer: tile (z, y0, x0) holds the 4x4 (y,x) patch of
// cells (z, y0..y0+3, x0..x0+3), 4 channels, fp16 -> 16 cells * 8B = 128B
// = one cache line. 32 MB total (L2-resident working set).
// uint4 j (j=0..7) holds cells 2j, 2j+1 (cell index c = dy*4+dx).
// Cell = {half2(ch0,ch1), half2(ch2,ch3)}.
__device__ uint4 g_tiles[NTILE * 8];

// ---------------------------------------------------------------------------
// Prep: build the tile buffer. One thread per (tile, dy): reads 4 cells
// (64B contiguous in knots), converts to fp16, writes 32B; warp writes are
// fully coalesced (1024B contiguous per warp).
// ---------------------------------------------------------------------------
__global__ void __launch_bounds__(256) k_prep(const float* __restrict__ knots)
{
    int tid = blockIdx.x * 256 + threadIdx.x;     // NTILE*4 threads
    int t  = tid >> 2;
    int dy = tid & 3;
    if (t >= NTILE) return;

    int z  = t >> 12;
    int y0 = (t >> 6) & 63;
    int x0 = t & 63;
    int y  = min(y0 + dy, GSZ - 1);

    const float4* src = reinterpret_cast<const float4*>(knots) + (z * GSZ + y) * GSZ;

    float4 k0 = src[min(x0 + 0, GSZ - 1)];
    float4 k1 = src[min(x0 + 1, GSZ - 1)];
    float4 k2 = src[min(x0 + 2, GSZ - 1)];
    float4 k3 = src[min(x0 + 3, GSZ - 1)];

    uint4 o0, o1;
    __half2 h;
    h = __floats2half2_rn(k0.x, k0.y); o0.x = *reinterpret_cast<unsigned*>(&h);
    h = __floats2half2_rn(k0.z, k0.w); o0.y = *reinterpret_cast<unsigned*>(&h);
    h = __floats2half2_rn(k1.x, k1.y); o0.z = *reinterpret_cast<unsigned*>(&h);
    h = __floats2half2_rn(k1.z, k1.w); o0.w = *reinterpret_cast<unsigned*>(&h);
    h = __floats2half2_rn(k2.x, k2.y); o1.x = *reinterpret_cast<unsigned*>(&h);
    h = __floats2half2_rn(k2.z, k2.w); o1.y = *reinterpret_cast<unsigned*>(&h);
    h = __floats2half2_rn(k3.x, k3.y); o1.z = *reinterpret_cast<unsigned*>(&h);
    h = __floats2half2_rn(k3.z, k3.w); o1.w = *reinterpret_cast<unsigned*>(&h);

    g_tiles[t * 8 + dy * 2 + 0] = o0;
    g_tiles[t * 8 + dy * 2 + 1] = o1;
}

// ---------------------------------------------------------------------------
// Main: quad mapping; lane lx owns y-row dy=lx. Per z: ONE 256-bit load
// (lane's 32B = its full y-row of the tile; the quad covers the whole 128B
// line in a single warp instruction -> 1 L1 wavefront per point per z).
// X-reduction in fp16 (hmul2/hfma2), z-accumulation in packed f32 (fma.rn.f32x2).
// ---------------------------------------------------------------------------
__global__ void __launch_bounds__(256) k_main(const float* __restrict__ coords,
                                              float* __restrict__ out,
                                              int n)
{
    int tid = blockIdx.x * 256 + threadIdx.x;
    int p  = tid >> 2;
    int lx = tid & 3;        // = y-tap dy of this lane
    if (p >= n) return;

    float zc = __ldg(&coords[p * 3 + 0]);
    float yc = __ldg(&coords[p * 3 + 1]);
    float xc = __ldg(&coords[p * 3 + 2]);

    float fz = floorf(zc), fy = floorf(yc), fx = floorf(xc);
    int iz = (int)fz, iy = (int)fy, ix = (int)fx;
    float sz = zc - fz, sy = yc - fy, sx = xc - fx;
    iz = min(max(iz, 1), GSZ - 3);
    iy = min(max(iy, 1), GSZ - 3);
    ix = min(max(ix, 1), GSZ - 3);

    // Catmull-Rom basis, z (all 4 taps needed per lane)
    float czv[4];
    czv[0] = sz * (-0.5f + sz * (1.0f - 0.5f * sz));
    czv[1] = 1.0f + sz * sz * (-2.5f + 1.5f * sz);
    czv[2] = sz * (0.5f + sz * (2.0f - 1.5f * sz));
    czv[3] = sz * sz * (0.5f * sz - 0.5f);

    // y: this lane needs only tap lx
    float cyl;
    {
        float c0 = sy * (-0.5f + sy * (1.0f - 0.5f * sy));
        float c1 = 1.0f + sy * sy * (-2.5f + 1.5f * sy);
        float c2 = sy * (0.5f + sy * (2.0f - 1.5f * sy));
        float c3 = sy * sy * (0.5f * sy - 0.5f);
        float ca = (lx & 1) ? c1 : c0;
        float cb = (lx & 1) ? c3 : c2;
        cyl = (lx & 2) ? cb : ca;
    }

    // x: all 4 taps, duplicated into half2 for the fp16 row-dot
    __half2 hx0, hx1, hx2, hx3;
    {
        float c0 = sx * (-0.5f + sx * (1.0f - 0.5f * sx));
        float c1 = 1.0f + sx * sx * (-2.5f + 1.5f * sx);
        float c2 = sx * (0.5f + sx * (2.0f - 1.5f * sx));
        float c3 = sx * sx * (0.5f * sx - 0.5f);
        hx0 = __float2half2_rn(c0);
        hx1 = __float2half2_rn(c1);
        hx2 = __float2half2_rn(c2);
        hx3 = __float2half2_rn(c3);
    }

    // lane's 32B slice (its y-row) of tile (z, iy-1, ix-1)
    const uint4* tbase = g_tiles
        + (size_t)(((iz - 1) * GSZ + (iy - 1)) * GSZ + (ix - 1)) * 8 + lx * 2;

    unsigned long long a01 = 0ull, a23 = 0ull;   // packed f32x2 accumulators

#pragma unroll
    for (int zi = 0; zi < 4; zi++) {
        const unsigned* tp = reinterpret_cast<const unsigned*>(
            tbase + (size_t)zi * (GSZ * GSZ * 8));

        unsigned r0, r1, r2, r3, r4, r5, r6, r7;
        asm("ld.global.nc.v8.b32 {%0,%1,%2,%3,%4,%5,%6,%7}, [%8];"
            : "=r"(r0), "=r"(r1), "=r"(r2), "=r"(r3),
              "=r"(r4), "=r"(r5), "=r"(r6), "=r"(r7)
            : "l"(tp));

        // r0 = cell(lx,0) ch01, r1 = cell(lx,0) ch23, r2 = cell(lx,1) ch01, ...
        __half2 c0_01 = *reinterpret_cast<__half2*>(&r0);
        __half2 c0_23 = *reinterpret_cast<__half2*>(&r1);
        __half2 c1_01 = *reinterpret_cast<__half2*>(&r2);
        __half2 c1_23 = *reinterpret_cast<__half2*>(&r3);
        __half2 c2_01 = *reinterpret_cast<__half2*>(&r4);
        __half2 c2_23 = *reinterpret_cast<__half2*>(&r5);
        __half2 c3_01 = *reinterpret_cast<__half2*>(&r6);
        __half2 c3_23 = *reinterpret_cast<__half2*>(&r7);

        // fp16 x-row dot (4 taps) for both channel pairs
        __half2 d01 = __hmul2(hx0, c0_01);
        d01 = __hfma2(hx1, c1_01, d01);
        d01 = __hfma2(hx2, c2_01, d01);
        d01 = __hfma2(hx3, c3_01, d01);
        __half2 d23 = __hmul2(hx0, c0_23);
        d23 = __hfma2(hx1, c1_23, d23);
        d23 = __hfma2(hx2, c2_23, d23);
        d23 = __hfma2(hx3, c3_23, d23);

        // f32 accumulate across z with packed FMA
        float wz = czv[zi] * cyl;
        float2 f01 = __half22float2(d01);
        float2 f23 = __half22float2(d23);

        unsigned long long wz2, v01, v23;
        asm("mov.b64 %0, {%1, %1};" : "=l"(wz2) : "f"(wz));
        asm("mov.b64 %0, {%1, %2};" : "=l"(v01) : "f"(f01.x), "f"(f01.y));
        asm("mov.b64 %0, {%1, %2};" : "=l"(v23) : "f"(f23.x), "f"(f23.y));
        asm("fma.rn.f32x2 %0, %1, %2, %3;" : "=l"(a01) : "l"(wz2), "l"(v01), "l"(a01));
        asm("fma.rn.f32x2 %0, %1, %2, %3;" : "=l"(a23) : "l"(wz2), "l"(v23), "l"(a23));
    }

    // unpack and reduce over the quad (y-taps)
    float a0, a1, a2, a3;
    asm("mov.b64 {%0, %1}, %2;" : "=f"(a0), "=f"(a1) : "l"(a01));
    asm("mov.b64 {%0, %1}, %2;" : "=f"(a2), "=f"(a3) : "l"(a23));

#pragma unroll
    for (int d = 1; d < 4; d <<= 1) {
        a0 += __shfl_xor_sync(0xffffffffu, a0, d);
        a1 += __shfl_xor_sync(0xffffffffu, a1, d);
        a2 += __shfl_xor_sync(0xffffffffu, a2, d);
        a3 += __shfl_xor_sync(0xffffffffu, a3, d);
    }

    if (lx == 0)
        reinterpret_cast<float4*>(out)[p] = make_float4(a0, a1, a2, a3);
}

// ---------------------------------------------------------------------------
extern "C" void kernel_launch(void* const* d_in, const int* in_sizes, int n_in,
                              void* d_out, int out_size) {
    const float* coords = (const float*)d_in[0];  // [N,3] f32
    const float* knots  = (const float*)d_in[1];  // [64,64,64,4] f32
    float* out          = (float*)d_out;          // [N,4] f32

    int n = in_sizes[0] / 3;

    int prep_threads = NTILE * 4;
    k_prep<<<(prep_threads + 255) / 256, 256>>>(knots);

    long long total = 4LL * n;
    k_main<<<(int)((total + 255) / 256), 256>>>(coords, out, n);
}